// round 1
// baseline (speedup 1.0000x reference)
#include <cuda_runtime.h>
#include <math.h>

#define DHEAD    128
#define BM       64
#define BN       64
#define WPAD     68          // padded row width for transposed Q/K smem tiles
#define NTHREADS 256

// log2(e)
#define LOG2E 1.4426950408889634f

// Flash attention, fp32 SIMT baseline.
// Grid: SQ/BM blocks. Block: 256 threads as 16x16 (ty, tx).
// Each thread: S fragment rows ty*4..ty*4+3, cols tx*4..tx*4+3 (phase A)
//              O fragment rows ty*4..ty*4+3, cols tx*8..tx*8+7 (phase B)
__global__ void __launch_bounds__(NTHREADS, 1)
sha_flash_fp32(const float* __restrict__ Q, const float* __restrict__ K,
               const float* __restrict__ V, float* __restrict__ O,
               int SK)
{
    extern __shared__ float smem[];
    float* sQT = smem;                       // [DHEAD][WPAD]  (transposed Q tile)
    float* sKT = sQT + DHEAD * WPAD;         // [DHEAD][WPAD]  (transposed K tile)
    float* sV  = sKT + DHEAD * WPAD;         // [BN][DHEAD]
    float* sP  = sV  + BN * DHEAD;           // [BM][BN]

    const int tid   = threadIdx.x;
    const int tx    = tid & 15;
    const int ty    = tid >> 4;
    const int qbase = blockIdx.x * BM;

    // ---- Load Q tile, transposed into smem: sQT[d][row] ----
    for (int i = tid; i < BM * DHEAD / 4; i += NTHREADS) {
        int row = i >> 5;            // 32 float4 per 128-wide row
        int d4  = (i & 31) * 4;
        float4 v = *(const float4*)&Q[(size_t)(qbase + row) * DHEAD + d4];
        sQT[(d4 + 0) * WPAD + row] = v.x;
        sQT[(d4 + 1) * WPAD + row] = v.y;
        sQT[(d4 + 2) * WPAD + row] = v.z;
        sQT[(d4 + 3) * WPAD + row] = v.w;
    }

    float m[4], l[4], o[4][8];
    #pragma unroll
    for (int r = 0; r < 4; r++) {
        m[r] = -INFINITY;
        l[r] = 0.0f;
        #pragma unroll
        for (int c = 0; c < 8; c++) o[r][c] = 0.0f;
    }

    for (int kb = 0; kb < SK; kb += BN) {
        __syncthreads();   // previous iteration's smem reads complete

        // ---- Load K tile (transposed) and V tile ----
        for (int i = tid; i < BN * DHEAD / 4; i += NTHREADS) {
            int row = i >> 5;
            int d4  = (i & 31) * 4;
            float4 kv = *(const float4*)&K[(size_t)(kb + row) * DHEAD + d4];
            sKT[(d4 + 0) * WPAD + row] = kv.x;
            sKT[(d4 + 1) * WPAD + row] = kv.y;
            sKT[(d4 + 2) * WPAD + row] = kv.z;
            sKT[(d4 + 3) * WPAD + row] = kv.w;
            *(float4*)&sV[row * DHEAD + d4] =
                *(const float4*)&V[(size_t)(kb + row) * DHEAD + d4];
        }
        __syncthreads();

        // ---- Phase A: S = Q K^T (4x4 fragment) ----
        float s[4][4];
        #pragma unroll
        for (int r = 0; r < 4; r++)
            #pragma unroll
            for (int c = 0; c < 4; c++) s[r][c] = 0.0f;

        #pragma unroll 8
        for (int d = 0; d < DHEAD; d++) {
            float4 qv = *(const float4*)&sQT[d * WPAD + ty * 4];
            float4 kv = *(const float4*)&sKT[d * WPAD + tx * 4];
            float qa[4] = {qv.x, qv.y, qv.z, qv.w};
            float ka[4] = {kv.x, kv.y, kv.z, kv.w};
            #pragma unroll
            for (int r = 0; r < 4; r++)
                #pragma unroll
                for (int c = 0; c < 4; c++)
                    s[r][c] = fmaf(qa[r], ka[c], s[r][c]);
        }

        // ---- Online softmax: row max across the 16 tx-threads ----
        float mt[4];
        #pragma unroll
        for (int r = 0; r < 4; r++)
            mt[r] = fmaxf(fmaxf(s[r][0], s[r][1]), fmaxf(s[r][2], s[r][3]));
        #pragma unroll
        for (int off = 1; off < 16; off <<= 1) {
            #pragma unroll
            for (int r = 0; r < 4; r++)
                mt[r] = fmaxf(mt[r], __shfl_xor_sync(0xffffffffu, mt[r], off));
        }

        float p[4][4], lt[4], alpha[4];
        #pragma unroll
        for (int r = 0; r < 4; r++) {
            float mn = fmaxf(m[r], mt[r]);
            alpha[r] = exp2f((m[r] - mn) * LOG2E);   // 0 when m was -inf
            lt[r] = 0.0f;
            #pragma unroll
            for (int c = 0; c < 4; c++) {
                p[r][c] = exp2f((s[r][c] - mn) * LOG2E);
                lt[r] += p[r][c];
            }
            m[r] = mn;
        }
        #pragma unroll
        for (int off = 1; off < 16; off <<= 1) {
            #pragma unroll
            for (int r = 0; r < 4; r++)
                lt[r] += __shfl_xor_sync(0xffffffffu, lt[r], off);
        }
        #pragma unroll
        for (int r = 0; r < 4; r++)
            l[r] = l[r] * alpha[r] + lt[r];

        // ---- Stage P to smem ----
        #pragma unroll
        for (int r = 0; r < 4; r++) {
            float4 pv = make_float4(p[r][0], p[r][1], p[r][2], p[r][3]);
            *(float4*)&sP[(ty * 4 + r) * BN + tx * 4] = pv;
        }
        __syncthreads();

        // ---- Rescale O, then O += P V ----
        #pragma unroll
        for (int r = 0; r < 4; r++)
            #pragma unroll
            for (int c = 0; c < 8; c++)
                o[r][c] *= alpha[r];

        #pragma unroll 4
        for (int kk = 0; kk < BN; kk++) {
            float4 v0 = *(const float4*)&sV[kk * DHEAD + tx * 8];
            float4 v1 = *(const float4*)&sV[kk * DHEAD + tx * 8 + 4];
            #pragma unroll
            for (int r = 0; r < 4; r++) {
                float pr = sP[(ty * 4 + r) * BN + kk];
                o[r][0] = fmaf(pr, v0.x, o[r][0]);
                o[r][1] = fmaf(pr, v0.y, o[r][1]);
                o[r][2] = fmaf(pr, v0.z, o[r][2]);
                o[r][3] = fmaf(pr, v0.w, o[r][3]);
                o[r][4] = fmaf(pr, v1.x, o[r][4]);
                o[r][5] = fmaf(pr, v1.y, o[r][5]);
                o[r][6] = fmaf(pr, v1.z, o[r][6]);
                o[r][7] = fmaf(pr, v1.w, o[r][7]);
            }
        }
    }

    // ---- Epilogue: divide by l, write out ----
    #pragma unroll
    for (int r = 0; r < 4; r++) {
        float inv = 1.0f / l[r];
        float4 w0 = make_float4(o[r][0] * inv, o[r][1] * inv,
                                o[r][2] * inv, o[r][3] * inv);
        float4 w1 = make_float4(o[r][4] * inv, o[r][5] * inv,
                                o[r][6] * inv, o[r][7] * inv);
        size_t base = (size_t)(qbase + ty * 4 + r) * DHEAD + tx * 8;
        *(float4*)&O[base]     = w0;
        *(float4*)&O[base + 4] = w1;
    }
}

extern "C" void kernel_launch(void* const* d_in, const int* in_sizes, int n_in,
                              void* d_out, int out_size)
{
    const float* Q = (const float*)d_in[0];
    const float* K = (const float*)d_in[1];
    const float* V = (const float*)d_in[2];
    float* O = (float*)d_out;

    int SQ = in_sizes[0] / DHEAD;
    int SK = in_sizes[1] / DHEAD;

    size_t smem_bytes = (size_t)(2 * DHEAD * WPAD + BN * DHEAD + BM * BN) * sizeof(float);
    cudaFuncSetAttribute(sha_flash_fp32,
                         cudaFuncAttributeMaxDynamicSharedMemorySize,
                         (int)smem_bytes);

    dim3 grid(SQ / BM);
    sha_flash_fp32<<<grid, NTHREADS, smem_bytes>>>(Q, K, V, O, SK);
}

// round 5
// speedup vs baseline: 7.4756x; 7.4756x over previous
#include <cuda_runtime.h>
#include <cuda_fp16.h>
#include <math.h>
#include <stdint.h>

#define SQc  8192
#define SKc  8192
#define DHc  128
#define BMc  128
#define BNc  64
#define KSPLIT 2
#define NTILES (SKc / KSPLIT / BNc)   // 64
#define NT   256

#define LOG2E 1.4426950408889634f

// ---------------- global scratch (static; no allocation) ----------------
__device__ __align__(256) __half g_Qh[SQc * DHc];
__device__ __align__(256) __half g_Ql[SQc * DHc];
__device__ __align__(256) __half g_Kh[SKc * DHc];
__device__ __align__(256) __half g_Kl[SKc * DHc];
__device__ __align__(256) __half g_Vt[DHc * SKc];     // V transposed: [d][key]
__device__ __align__(256) float g_Opart[KSPLIT][SQc * DHc];
__device__ __align__(256) float g_lpart[KSPLIT][SQc];
__device__ __align__(256) float g_mpart[KSPLIT][SQc]; // row max, log2 domain

// ---------------- helpers ----------------
__device__ __forceinline__ uint32_t sw128(uint32_t o) { return o ^ ((o >> 3) & 0x70); }

__device__ __forceinline__ uint32_t smem_u32(const void* p) {
    uint32_t a;
    asm("{ .reg .u64 t; cvta.to.shared.u64 t, %1; cvt.u32.u64 %0, t; }" : "=r"(a) : "l"(p));
    return a;
}

__device__ __forceinline__ void cp16(uint32_t dst, const void* src) {
    asm volatile("cp.async.cg.shared.global [%0], [%1], 16;" :: "r"(dst), "l"(src));
}
__device__ __forceinline__ void cp_commit() { asm volatile("cp.async.commit_group;" ::: "memory"); }

__device__ __forceinline__ void ldsm4(uint32_t* r, uint32_t addr) {
    asm volatile("ldmatrix.sync.aligned.m8n8.x4.shared.b16 {%0,%1,%2,%3}, [%4];"
        : "=r"(r[0]), "=r"(r[1]), "=r"(r[2]), "=r"(r[3]) : "r"(addr));
}

__device__ __forceinline__ void mma16816(float* d, const uint32_t* a, uint32_t b0, uint32_t b1) {
    asm volatile(
        "mma.sync.aligned.m16n8k16.row.col.f32.f16.f16.f32 "
        "{%0,%1,%2,%3}, {%4,%5,%6,%7}, {%8,%9}, {%0,%1,%2,%3};"
        : "+f"(d[0]), "+f"(d[1]), "+f"(d[2]), "+f"(d[3])
        : "r"(a[0]), "r"(a[1]), "r"(a[2]), "r"(a[3]), "r"(b0), "r"(b1));
}

__device__ __forceinline__ float ex2f(float x) {
    float r;
    asm("ex2.approx.f32 %0, %1;" : "=f"(r) : "f"(x));
    return r;
}

__device__ __forceinline__ uint32_t packh2(float lo, float hi) {
    uint32_t u;
    asm("cvt.rn.f16x2.f32 %0, %1, %2;" : "=r"(u) : "f"(hi), "f"(lo));
    return u;
}

// ---------------- preprocessing ----------------
__global__ void convert_qk(const float* __restrict__ Q, const float* __restrict__ K) {
    int i = blockIdx.x * 256 + threadIdx.x;
    float q = Q[i];
    __half h = __float2half_rn(q);
    g_Qh[i] = h;
    g_Ql[i] = __float2half_rn(q - __half2float(h));
    float k = K[i];
    h = __float2half_rn(k);
    g_Kh[i] = h;
    g_Kl[i] = __float2half_rn(k - __half2float(h));
}

__global__ void convert_vt(const float* __restrict__ V) {
    __shared__ float t[32][33];
    int s0 = blockIdx.x * 32, d0 = blockIdx.y * 32;
    int tx = threadIdx.x, ty = threadIdx.y;   // 32 x 8
    #pragma unroll
    for (int i = 0; i < 4; i++)
        t[ty * 4 + i][tx] = V[(size_t)(s0 + ty * 4 + i) * DHc + d0 + tx];
    __syncthreads();
    #pragma unroll
    for (int i = 0; i < 4; i++)
        g_Vt[(size_t)(d0 + ty * 4 + i) * SKc + s0 + tx] = __float2half_rn(t[tx][ty * 4 + i]);
}

__global__ void combine_out(float* __restrict__ O) {
    int i = blockIdx.x * 256 + threadIdx.x;
    int row = i >> 7;
    float m0 = g_mpart[0][row], m1 = g_mpart[1][row];
    float M = fmaxf(m0, m1);
    float w0 = exp2f(m0 - M), w1 = exp2f(m1 - M);
    float l = g_lpart[0][row] * w0 + g_lpart[1][row] * w1;
    O[i] = (g_Opart[0][i] * w0 + g_Opart[1][i] * w1) / l;
}

// ---------------- main kernel ----------------
// stage: Kh c0 @0 (8K), Kh c1 @8192, Kl c0 @16384, Kl c1 @24576, Vt @32768 (16K)
#define STG        49152
#define QLB_OFF    (3 * STG)
#define SMEM_TOTAL (3 * STG + 32768)

__device__ __forceinline__ void load_tile(uint32_t SB, int kb, int tid) {
    #pragma unroll
    for (int it = 0; it < 12; it++) {
        int u = it * NT + tid;
        if (u < 2048) {                 // K: split(hi/lo) x chunk x 64 rows x 8 units
            int sp = u >> 10;
            int i  = u & 1023;
            int ch = i >> 9;
            int r  = (i >> 3) & 63;
            int cb = i & 7;
            uint32_t dst = SB + (uint32_t)sp * 16384u + (uint32_t)ch * 8192u
                         + sw128((uint32_t)(r * 128 + cb * 16));
            const __half* src = (sp ? g_Kl : g_Kh) + ((size_t)(kb + r) * DHc + ch * 64 + cb * 8);
            cp16(dst, src);
        } else {                        // Vt: 128 rows x 8 units
            int v  = u - 2048;
            int r  = v >> 3;
            int cb = v & 7;
            uint32_t dst = SB + 32768u + sw128((uint32_t)(r * 128 + cb * 16));
            const __half* src = g_Vt + ((size_t)r * SKc + kb + cb * 8);
            cp16(dst, src);
        }
    }
}

__global__ void __launch_bounds__(NT, 1) attn_hmma() {
    extern __shared__ char smem[];
    const uint32_t sb  = smem_u32(smem);
    const uint32_t QLB = sb + QLB_OFF;
    const int tid   = threadIdx.x;
    const int w     = tid >> 5;
    const int lane  = tid & 31;
    const int wbase = w * 16;
    const int qb    = blockIdx.x * BMc;
    const int ky    = blockIdx.y;
    const int kb0   = ky * (SKc / KSPLIT);

    // ---- stage Q: Qh -> stage0 region (transient), Ql -> dedicated region ----
    #pragma unroll
    for (int it = 0; it < 16; it++) {
        int u  = it * NT + tid;         // 0..4095
        int sp = u >> 11;               // 0: hi, 1: lo
        int i  = u & 2047;
        int ch = i >> 10;
        int r  = (i >> 3) & 127;
        int cb = i & 7;
        uint32_t base = sp ? QLB : sb;
        uint32_t dst  = base + (uint32_t)ch * 16384u + sw128((uint32_t)(r * 128 + cb * 16));
        const __half* src = (sp ? g_Ql : g_Qh) + ((size_t)(qb + r) * DHc + ch * 64 + cb * 8);
        cp16(dst, src);
    }
    cp_commit();
    asm volatile("cp.async.wait_group 0;" ::: "memory");
    __syncthreads();

    // ---- Qh A-fragments -> registers (8 ksteps x 4 regs) ----
    uint32_t qh[8][4];
    {
        int arow = wbase + ((lane >> 3) & 1) * 8 + (lane & 7);
        int ab   = (lane >> 4) * 16;
        #pragma unroll
        for (int ks = 0; ks < 8; ks++) {
            int ch  = ks >> 2;
            int dby = (ks & 3) * 32 + ab;
            ldsm4(qh[ks], sb + (uint32_t)ch * 16384u + sw128((uint32_t)(arow * 128 + dby)));
        }
    }
    __syncthreads();   // all warps done reading Qh staging before K tiles overwrite it

    // prologue: tiles 0 and 1
    load_tile(sb + 0 * STG, kb0 + 0 * BNc, tid); cp_commit();
    load_tile(sb + 1 * STG, kb0 + 1 * BNc, tid); cp_commit();

    float o[16][4];
    #pragma unroll
    for (int n = 0; n < 16; n++)
        #pragma unroll
        for (int j = 0; j < 4; j++) o[n][j] = 0.0f;
    float m0 = -INFINITY, m1 = -INFINITY, l0 = 0.0f, l1 = 0.0f;

    // precomputed lane addresses
    const int krow_b = (lane & 7) * 128 + ((lane >> 3) & 3) * 16;          // K ldmatrix
    const int arow   = wbase + ((lane >> 3) & 1) * 8 + (lane & 7);          // Q/Ql ldmatrix
    const int adb    = (lane >> 4) * 16;
    const int vrow_b = (((lane >> 4) & 1) * 8 + (lane & 7)) * 128 + ((lane >> 3) & 1) * 16; // Vt

    for (int t = 0; t < NTILES; t++) {
        const uint32_t SB = sb + (uint32_t)(t % 3) * STG;

        if (t == NTILES - 1) asm volatile("cp.async.wait_group 0;" ::: "memory");
        else                 asm volatile("cp.async.wait_group 1;" ::: "memory");
        __syncthreads();

        if (t + 2 < NTILES) {
            load_tile(sb + (uint32_t)((t + 2) % 3) * STG, kb0 + (t + 2) * BNc, tid);
            cp_commit();
        }

        // ---- S = (Qh+Ql)(Kh+Kl)^T, 3 split passes interleaved ----
        float s[8][4];
        #pragma unroll
        for (int n = 0; n < 8; n++)
            #pragma unroll
            for (int j = 0; j < 4; j++) s[n][j] = 0.0f;

        #pragma unroll
        for (int ch = 0; ch < 2; ch++) {
            #pragma unroll
            for (int ks2 = 0; ks2 < 2; ks2++) {
                const int ksA = ch * 4 + ks2 * 2;
                uint32_t bh[8][4];
                #pragma unroll
                for (int n = 0; n < 8; n++)
                    ldsm4(bh[n], SB + (uint32_t)ch * 8192u
                                 + sw128((uint32_t)(n * 1024 + ks2 * 64 + krow_b)));
                // Ql fragments for these two ksteps
                uint32_t qlf[2][4];
                #pragma unroll
                for (int kd = 0; kd < 2; kd++) {
                    int ks  = ksA + kd;
                    int dby = (ks & 3) * 32 + adb;
                    ldsm4(qlf[kd], QLB + (uint32_t)ch * 16384u
                                   + sw128((uint32_t)(arow * 128 + dby)));
                }
                #pragma unroll
                for (int n = 0; n < 8; n++) {
                    mma16816(s[n], qh[ksA],     bh[n][0], bh[n][1]);
                    mma16816(s[n], qh[ksA + 1], bh[n][2], bh[n][3]);
                    mma16816(s[n], qlf[0],      bh[n][0], bh[n][1]);
                    mma16816(s[n], qlf[1],      bh[n][2], bh[n][3]);
                }
                uint32_t bl[8][4];
                #pragma unroll
                for (int n = 0; n < 8; n++)
                    ldsm4(bl[n], SB + 16384u + (uint32_t)ch * 8192u
                                 + sw128((uint32_t)(n * 1024 + ks2 * 64 + krow_b)));
                #pragma unroll
                for (int n = 0; n < 8; n++) {
                    mma16816(s[n], qh[ksA],     bl[n][0], bl[n][1]);
                    mma16816(s[n], qh[ksA + 1], bl[n][2], bl[n][3]);
                }
            }
        }

        // ---- online softmax (log2 domain) ----
        #pragma unroll
        for (int n = 0; n < 8; n++)
            #pragma unroll
            for (int j = 0; j < 4; j++) s[n][j] *= LOG2E;

        float t0 = s[0][0], t1 = s[0][2];
        #pragma unroll
        for (int n = 0; n < 8; n++) {
            t0 = fmaxf(t0, fmaxf(s[n][0], s[n][1]));
            t1 = fmaxf(t1, fmaxf(s[n][2], s[n][3]));
        }
        t0 = fmaxf(t0, __shfl_xor_sync(0xffffffffu, t0, 1));
        t0 = fmaxf(t0, __shfl_xor_sync(0xffffffffu, t0, 2));
        t1 = fmaxf(t1, __shfl_xor_sync(0xffffffffu, t1, 1));
        t1 = fmaxf(t1, __shfl_xor_sync(0xffffffffu, t1, 2));

        float mn0 = fmaxf(m0, t0), mn1 = fmaxf(m1, t1);
        float a0 = ex2f(m0 - mn0), a1 = ex2f(m1 - mn1);
        m0 = mn0; m1 = mn1;
        l0 *= a0; l1 *= a1;
        #pragma unroll
        for (int n = 0; n < 16; n++) {
            o[n][0] *= a0; o[n][1] *= a0;
            o[n][2] *= a1; o[n][3] *= a1;
        }

        uint32_t ph[8][2];
        #pragma unroll
        for (int n = 0; n < 8; n++) {
            float p0 = ex2f(s[n][0] - mn0);
            float p1 = ex2f(s[n][1] - mn0);
            float p2 = ex2f(s[n][2] - mn1);
            float p3 = ex2f(s[n][3] - mn1);
            l0 += p0 + p1;
            l1 += p2 + p3;
            ph[n][0] = packh2(p0, p1);
            ph[n][1] = packh2(p2, p3);
        }

        // ---- O += P V ----
        #pragma unroll
        for (int ks = 0; ks < 4; ks++) {
            uint32_t A[4] = { ph[2 * ks][0], ph[2 * ks][1], ph[2 * ks + 1][0], ph[2 * ks + 1][1] };
            uint32_t bv[8][4];
            #pragma unroll
            for (int dp = 0; dp < 8; dp++)
                ldsm4(bv[dp], SB + 32768u
                              + sw128((uint32_t)(dp * 2048 + ks * 32 + vrow_b)));
            #pragma unroll
            for (int dp = 0; dp < 8; dp++) {
                mma16816(o[2 * dp],     A, bv[dp][0], bv[dp][1]);
                mma16816(o[2 * dp + 1], A, bv[dp][2], bv[dp][3]);
            }
        }
    }

    // ---- epilogue ----
    l0 += __shfl_xor_sync(0xffffffffu, l0, 1);
    l0 += __shfl_xor_sync(0xffffffffu, l0, 2);
    l1 += __shfl_xor_sync(0xffffffffu, l1, 1);
    l1 += __shfl_xor_sync(0xffffffffu, l1, 2);

    int r0 = qb + wbase + (lane >> 2);
    int r1 = r0 + 8;
    int c2 = (lane & 3) * 2;
    float* op = g_Opart[ky];
    #pragma unroll
    for (int n = 0; n < 16; n++) {
        *(float2*)&op[(size_t)r0 * DHc + n * 8 + c2] = make_float2(o[n][0], o[n][1]);
        *(float2*)&op[(size_t)r1 * DHc + n * 8 + c2] = make_float2(o[n][2], o[n][3]);
    }
    if ((lane & 3) == 0) {
        g_lpart[ky][r0] = l0;  g_lpart[ky][r1] = l1;
        g_mpart[ky][r0] = m0;  g_mpart[ky][r1] = m1;
    }
}

// ---------------- launcher ----------------
extern "C" void kernel_launch(void* const* d_in, const int* in_sizes, int n_in,
                              void* d_out, int out_size)
{
    const float* Q = (const float*)d_in[0];
    const float* K = (const float*)d_in[1];
    const float* V = (const float*)d_in[2];
    float* O = (float*)d_out;

    cudaFuncSetAttribute(attn_hmma, cudaFuncAttributeMaxDynamicSharedMemorySize, SMEM_TOTAL);

    convert_qk<<<SQc * DHc / 256, 256>>>(Q, K);
    convert_vt<<<dim3(SKc / 32, DHc / 32), dim3(32, 8)>>>(V);
    attn_hmma<<<dim3(SQc / BMc, KSPLIT), NT, SMEM_TOTAL>>>();
    combine_out<<<SQc * DHc / 256, 256>>>(O);
}